// round 6
// baseline (speedup 1.0000x reference)
#include <cuda_runtime.h>

// Resample (upfirdn2d, FIR=[1,3,3,1], up=2)
// x: (4,256,128,128) f32 -> out: (4,256,256,256) f32
//
//   out row 2m   = 1*x[m-1] + 3*x[m]
//   out row 2m+1 = 3*x[m]   + 1*x[m+1]
//   out col 2n   = 1*x[n-2] + 3*x[n-1]
//   out col 2n+1 = 3*x[n-1] + 1*x[n]
//   scale 1/16; out-of-range -> 0.
//
// R5: one warp spans a full 128-col input row; each lane holds one float4
// (cols 4t..4t+3). 6 LDG.128 per thread for 4 input rows (8 output rows).
// Left halo = prev lane's vertical-FIR .z/.w via 4 shuffles per row.
// Lane 0 is the true image border (zeros) — no wrap path.

#define H_IN  128
#define W_IN  128
#define W_OUT 256
#define BC    (4 * 256)
#define ROWS  4

__global__ __launch_bounds__(256) void upfir_up2_kernel(const float* __restrict__ x,
                                                        float* __restrict__ out) {
    const int lane = threadIdx.x;                                    // 0..31, input cols 4t..4t+3
    const int m0   = (blockIdx.y * blockDim.y + threadIdx.y) * ROWS; // 0,4,...,124
    const int bc   = blockIdx.z;

    const float* __restrict__ xin = x + (size_t)bc * (H_IN * W_IN);
    float* __restrict__ o         = out + (size_t)bc * (2 * H_IN) * W_OUT;

    // Rows m0-1 .. m0+ROWS at indices 0..ROWS+1.
    float4 a[ROWS + 2];

    // Interior rows: unconditional, front-batched.
#pragma unroll
    for (int i = 1; i <= ROWS; i++) {
        const float4* row = (const float4*)(xin + (size_t)(m0 - 1 + i) * W_IN);
        a[i] = __ldg(row + lane);
    }
    // Halo rows (border-predicated only).
    a[0]        = make_float4(0.f, 0.f, 0.f, 0.f);
    a[ROWS + 1] = make_float4(0.f, 0.f, 0.f, 0.f);
    if (m0 > 0)
        a[0] = __ldg((const float4*)(xin + (size_t)(m0 - 1) * W_IN) + lane);
    if (m0 + ROWS < H_IN)
        a[ROWS + 1] = __ldg((const float4*)(xin + (size_t)(m0 + ROWS) * W_IN) + lane);

    const float s = 1.f / 16.f;
#pragma unroll
    for (int i = 0; i < ROWS; i++) {
        // Vertical FIR (row m = m0+i at index i+1).
        float4 e, d;
        e.x = a[i].x + 3.f * a[i + 1].x;  e.y = a[i].y + 3.f * a[i + 1].y;
        e.z = a[i].z + 3.f * a[i + 1].z;  e.w = a[i].w + 3.f * a[i + 1].w;
        d.x = 3.f * a[i + 1].x + a[i + 2].x;  d.y = 3.f * a[i + 1].y + a[i + 2].y;
        d.z = 3.f * a[i + 1].z + a[i + 2].z;  d.w = 3.f * a[i + 1].w + a[i + 2].w;

        // Halo: prev lane's v[4t-2], v[4t-1] (.z, .w). Lane 0 -> zeros (true border).
        float pez = __shfl_up_sync(0xffffffffu, e.z, 1);
        float pew = __shfl_up_sync(0xffffffffu, e.w, 1);
        float pdz = __shfl_up_sync(0xffffffffu, d.z, 1);
        float pdw = __shfl_up_sync(0xffffffffu, d.w, 1);
        if (lane == 0) { pez = pew = pdz = pdw = 0.f; }

        // Horizontal FIR -> output cols 8t..8t+7 for rows 2m, 2m+1.
        float4 e0 = make_float4((pez + 3.f * pew) * s, (3.f * pew + e.x) * s,
                                (pew + 3.f * e.x) * s, (3.f * e.x + e.y) * s);
        float4 e1 = make_float4((e.x + 3.f * e.y) * s, (3.f * e.y + e.z) * s,
                                (e.y + 3.f * e.z) * s, (3.f * e.z + e.w) * s);
        float4 d0 = make_float4((pdz + 3.f * pdw) * s, (3.f * pdw + d.x) * s,
                                (pdw + 3.f * d.x) * s, (3.f * d.x + d.y) * s);
        float4 d1 = make_float4((d.x + 3.f * d.y) * s, (3.f * d.y + d.z) * s,
                                (d.y + 3.f * d.z) * s, (3.f * d.z + d.w) * s);

        const int m = m0 + i;
        float4* re = (float4*)(o + (size_t)(2 * m) * W_OUT);
        float4* rd = (float4*)(o + (size_t)(2 * m + 1) * W_OUT);
        __stcs(re + 2 * lane, e0);         // contiguous 1 KB per warp per row
        __stcs(re + 2 * lane + 1, e1);
        __stcs(rd + 2 * lane, d0);
        __stcs(rd + 2 * lane + 1, d1);
    }
}

extern "C" void kernel_launch(void* const* d_in, const int* in_sizes, int n_in,
                              void* d_out, int out_size) {
    const float* x = (const float*)d_in[0];
    float* out = (float*)d_out;

    dim3 block(32, 8, 1);                    // 256 threads: 1 warp x 8 row-groups
    dim3 grid(1, H_IN / (8 * ROWS), BC);     // (1, 4, 1024)
    upfir_up2_kernel<<<grid, block>>>(x, out);
}

// round 7
// speedup vs baseline: 1.4495x; 1.4495x over previous
#include <cuda_runtime.h>
#include <cstdint>

// Resample (upfirdn2d, FIR=[1,3,3,1], up=2)
// x: (4,256,128,128) f32 -> out: (4,256,256,256) f32
//
//   out row 2m   = 1*x[m-1] + 3*x[m]
//   out row 2m+1 = 3*x[m]   + 1*x[m+1]
//   out col 2n   = 1*x[n-2] + 3*x[n-1]
//   out col 2n+1 = 3*x[n-1] + 1*x[n]
//   scale 1/16; out-of-range -> 0.
//
// R6: R4 compute (warp spans row as two float2 halves, shuffle halo) +
// TMA bulk-store epilogue: each warp stages 2 output rows (2 KB) in SMEM
// (double-buffered) and issues cp.async.bulk.global.shared::cta, removing
// the STG wavefront load from the L1/LSU path.

#define H_IN  128
#define W_IN  128
#define W_OUT 256
#define BC    (4 * 256)
#define ROWS  4
#define WARPS 8

__device__ __forceinline__ uint32_t smem_u32(const void* p) {
    return (uint32_t)__cvta_generic_to_shared(p);
}

__device__ __forceinline__ float2 prev_lane_or_zero(float2 v, int lane) {
    float2 p;
    p.x = __shfl_up_sync(0xffffffffu, v.x, 1);
    p.y = __shfl_up_sync(0xffffffffu, v.y, 1);
    if (lane == 0) { p.x = 0.f; p.y = 0.f; }
    return p;
}

__device__ __forceinline__ float2 prev_lane_or_wrap(float2 v, float2 wrapSrc, int lane) {
    float2 p;
    p.x = __shfl_up_sync(0xffffffffu, v.x, 1);
    p.y = __shfl_up_sync(0xffffffffu, v.y, 1);
    const float wx = __shfl_sync(0xffffffffu, wrapSrc.x, 31);
    const float wy = __shfl_sync(0xffffffffu, wrapSrc.y, 31);
    if (lane == 0) { p.x = wx; p.y = wy; }
    return p;
}

__global__ __launch_bounds__(256) void upfir_up2_kernel(const float* __restrict__ x,
                                                        float* __restrict__ out) {
    __shared__ float4 stage[WARPS][2][128];   // 2 x 2KB per warp

    const int lane = threadIdx.x;                                   // 0..31
    const int w    = threadIdx.y;                                   // 0..7
    const int m0   = (blockIdx.y * WARPS + w) * ROWS;               // 0,4,...,124
    const int bc   = blockIdx.z;

    const float2* __restrict__ xin = (const float2*)(x + (size_t)bc * (H_IN * W_IN));
    float* __restrict__ o          = out + (size_t)bc * (2 * H_IN) * W_OUT;

    // Rows m0-1 .. m0+ROWS at indices 0..ROWS+1; two 64-col halves per row.
    float2 a[ROWS + 2], b[ROWS + 2];

#pragma unroll
    for (int i = 1; i <= ROWS; i++) {
        const float2* row = xin + (size_t)(m0 - 1 + i) * (W_IN / 2);
        a[i] = __ldg(row + lane);        // cols 2t, 2t+1
        b[i] = __ldg(row + 32 + lane);   // cols 64+2t, 65+2t
    }
    a[0] = make_float2(0.f, 0.f); b[0] = a[0];
    a[ROWS + 1] = a[0];           b[ROWS + 1] = a[0];
    if (m0 > 0) {
        const float2* row = xin + (size_t)(m0 - 1) * (W_IN / 2);
        a[0] = __ldg(row + lane);
        b[0] = __ldg(row + 32 + lane);
    }
    if (m0 + ROWS < H_IN) {
        const float2* row = xin + (size_t)(m0 + ROWS) * (W_IN / 2);
        a[ROWS + 1] = __ldg(row + lane);
        b[ROWS + 1] = __ldg(row + 32 + lane);
    }

    const float s = 1.f / 16.f;
#pragma unroll
    for (int i = 0; i < ROWS; i++) {
        // Vertical FIR on own columns (row m = m0+i at index i+1).
        float2 eA, dA, eB, dB;
        eA.x = a[i].x + 3.f * a[i + 1].x;     eA.y = a[i].y + 3.f * a[i + 1].y;
        dA.x = 3.f * a[i + 1].x + a[i + 2].x; dA.y = 3.f * a[i + 1].y + a[i + 2].y;
        eB.x = b[i].x + 3.f * b[i + 1].x;     eB.y = b[i].y + 3.f * b[i + 1].y;
        dB.x = 3.f * b[i + 1].x + b[i + 2].x; dB.y = 3.f * b[i + 1].y + b[i + 2].y;

        const float2 peA = prev_lane_or_zero(eA, lane);
        const float2 pdA = prev_lane_or_zero(dA, lane);
        const float2 peB = prev_lane_or_wrap(eB, eA, lane);  // halfB lane0 <- halfA lane31
        const float2 pdB = prev_lane_or_wrap(dB, dA, lane);

        // Horizontal FIR -> 4 output cols per half per output row.
        float4 oEA = make_float4((peA.x + 3.f * peA.y) * s, (3.f * peA.y + eA.x) * s,
                                 (peA.y + 3.f * eA.x) * s,  (3.f * eA.x + eA.y) * s);
        float4 oDA = make_float4((pdA.x + 3.f * pdA.y) * s, (3.f * pdA.y + dA.x) * s,
                                 (pdA.y + 3.f * dA.x) * s,  (3.f * dA.x + dA.y) * s);
        float4 oEB = make_float4((peB.x + 3.f * peB.y) * s, (3.f * peB.y + eB.x) * s,
                                 (peB.y + 3.f * eB.x) * s,  (3.f * eB.x + eB.y) * s);
        float4 oDB = make_float4((pdB.x + 3.f * pdB.y) * s, (3.f * pdB.y + dB.x) * s,
                                 (pdB.y + 3.f * dB.x) * s,  (3.f * dB.x + dB.y) * s);

        const int buf = i & 1;

        // Before overwriting this buffer, make sure the bulk store issued
        // 2 iterations ago has READ the SMEM (allow 1 group outstanding).
        if (i >= 2) {
            if (lane == 0)
                asm volatile("cp.async.bulk.wait_group.read 1;" ::: "memory");
            __syncwarp();
        }

        // Stage rows 2m (first 64 float4) and 2m+1 (next 64), contiguous.
        float4* st = &stage[w][buf][0];
        st[lane]      = oEA;
        st[32 + lane] = oEB;
        st[64 + lane] = oDA;
        st[96 + lane] = oDB;

        // Publish generic-proxy STS to the async proxy, then issue bulk store.
        asm volatile("fence.proxy.async.shared::cta;" ::: "memory");
        __syncwarp();
        if (lane == 0) {
            const int m = m0 + i;
            void* gdst = (void*)(o + (size_t)(2 * m) * W_OUT);   // 2KB: rows 2m,2m+1
            asm volatile("cp.async.bulk.global.shared::cta.bulk_group [%0], [%1], 2048;"
                         :: "l"(gdst), "r"(smem_u32(st)) : "memory");
            asm volatile("cp.async.bulk.commit_group;" ::: "memory");
        }
    }

    // Drain all outstanding bulk stores before CTA exit (SMEM lifetime).
    if (lane == 0)
        asm volatile("cp.async.bulk.wait_group 0;" ::: "memory");
    __syncwarp();
}

extern "C" void kernel_launch(void* const* d_in, const int* in_sizes, int n_in,
                              void* d_out, int out_size) {
    const float* x = (const float*)d_in[0];
    float* out = (float*)d_out;

    dim3 block(32, WARPS, 1);                   // 256 threads
    dim3 grid(1, H_IN / (WARPS * ROWS), BC);    // (1, 4, 1024)
    upfir_up2_kernel<<<grid, block>>>(x, out);
}

// round 8
// speedup vs baseline: 1.4770x; 1.0190x over previous
#include <cuda_runtime.h>
#include <cstdint>

// Resample (upfirdn2d, FIR=[1,3,3,1], up=2)
// x: (4,256,128,128) f32 -> out: (4,256,256,256) f32
//
//   out row 2m   = 1*x[m-1] + 3*x[m]
//   out row 2m+1 = 3*x[m]   + 1*x[m+1]
//   out col 2n   = 1*x[n-2] + 3*x[n-1]
//   out col 2n+1 = 3*x[n-1] + 1*x[n]
//   scale 1/16; out-of-range -> 0.
//
// R7: R4 compute core (warp spans row as two float2 halves, shuffle halo).
// Each warp stages its FULL output tile (8 output rows = 8 KB, contiguous in
// gmem) in SMEM and emits ONE cp.async.bulk at the end: maximal write burst
// length, one fence per warp, zero buffer-reuse waits.

#define H_IN  128
#define W_IN  128
#define W_OUT 256
#define BC    (4 * 256)
#define ROWS  4
#define WARPS 4

__device__ __forceinline__ uint32_t smem_u32(const void* p) {
    return (uint32_t)__cvta_generic_to_shared(p);
}

__device__ __forceinline__ float2 prev_lane_or_zero(float2 v, int lane) {
    float2 p;
    p.x = __shfl_up_sync(0xffffffffu, v.x, 1);
    p.y = __shfl_up_sync(0xffffffffu, v.y, 1);
    if (lane == 0) { p.x = 0.f; p.y = 0.f; }
    return p;
}

__device__ __forceinline__ float2 prev_lane_or_wrap(float2 v, float2 wrapSrc, int lane) {
    float2 p;
    p.x = __shfl_up_sync(0xffffffffu, v.x, 1);
    p.y = __shfl_up_sync(0xffffffffu, v.y, 1);
    const float wx = __shfl_sync(0xffffffffu, wrapSrc.x, 31);
    const float wy = __shfl_sync(0xffffffffu, wrapSrc.y, 31);
    if (lane == 0) { p.x = wx; p.y = wy; }
    return p;
}

__global__ __launch_bounds__(128) void upfir_up2_kernel(const float* __restrict__ x,
                                                        float* __restrict__ out) {
    __shared__ float4 stage[WARPS][512];   // 8 KB per warp = 8 output rows

    const int lane = threadIdx.x;                       // 0..31
    const int w    = threadIdx.y;                       // 0..3
    const int m0   = (blockIdx.y * WARPS + w) * ROWS;   // 0,4,...,124
    const int bc   = blockIdx.z;

    const float2* __restrict__ xin = (const float2*)(x + (size_t)bc * (H_IN * W_IN));
    float* __restrict__ o          = out + (size_t)bc * (2 * H_IN) * W_OUT;

    // Rows m0-1 .. m0+ROWS at indices 0..ROWS+1; two 64-col halves per row.
    float2 a[ROWS + 2], b[ROWS + 2];

#pragma unroll
    for (int i = 1; i <= ROWS; i++) {
        const float2* row = xin + (size_t)(m0 - 1 + i) * (W_IN / 2);
        a[i] = __ldg(row + lane);        // cols 2t, 2t+1
        b[i] = __ldg(row + 32 + lane);   // cols 64+2t, 65+2t
    }
    a[0] = make_float2(0.f, 0.f); b[0] = a[0];
    a[ROWS + 1] = a[0];           b[ROWS + 1] = a[0];
    if (m0 > 0) {
        const float2* row = xin + (size_t)(m0 - 1) * (W_IN / 2);
        a[0] = __ldg(row + lane);
        b[0] = __ldg(row + 32 + lane);
    }
    if (m0 + ROWS < H_IN) {
        const float2* row = xin + (size_t)(m0 + ROWS) * (W_IN / 2);
        a[ROWS + 1] = __ldg(row + lane);
        b[ROWS + 1] = __ldg(row + 32 + lane);
    }

    const float s = 1.f / 16.f;
    float4* st = &stage[w][0];
#pragma unroll
    for (int i = 0; i < ROWS; i++) {
        // Vertical FIR on own columns (row m = m0+i at index i+1).
        float2 eA, dA, eB, dB;
        eA.x = a[i].x + 3.f * a[i + 1].x;     eA.y = a[i].y + 3.f * a[i + 1].y;
        dA.x = 3.f * a[i + 1].x + a[i + 2].x; dA.y = 3.f * a[i + 1].y + a[i + 2].y;
        eB.x = b[i].x + 3.f * b[i + 1].x;     eB.y = b[i].y + 3.f * b[i + 1].y;
        dB.x = 3.f * b[i + 1].x + b[i + 2].x; dB.y = 3.f * b[i + 1].y + b[i + 2].y;

        const float2 peA = prev_lane_or_zero(eA, lane);
        const float2 pdA = prev_lane_or_zero(dA, lane);
        const float2 peB = prev_lane_or_wrap(eB, eA, lane);  // halfB lane0 <- halfA lane31
        const float2 pdB = prev_lane_or_wrap(dB, dA, lane);

        // Horizontal FIR -> 4 output cols per half per output row.
        float4 oEA = make_float4((peA.x + 3.f * peA.y) * s, (3.f * peA.y + eA.x) * s,
                                 (peA.y + 3.f * eA.x) * s,  (3.f * eA.x + eA.y) * s);
        float4 oDA = make_float4((pdA.x + 3.f * pdA.y) * s, (3.f * pdA.y + dA.x) * s,
                                 (pdA.y + 3.f * dA.x) * s,  (3.f * dA.x + dA.y) * s);
        float4 oEB = make_float4((peB.x + 3.f * peB.y) * s, (3.f * peB.y + eB.x) * s,
                                 (peB.y + 3.f * eB.x) * s,  (3.f * eB.x + eB.y) * s);
        float4 oDB = make_float4((pdB.x + 3.f * pdB.y) * s, (3.f * pdB.y + dB.x) * s,
                                 (pdB.y + 3.f * dB.x) * s,  (3.f * dB.x + dB.y) * s);

        // Stage rows 2(m0+i), 2(m0+i)+1 at float4 offsets 128*i .. 128*i+127.
        st[128 * i + lane]      = oEA;
        st[128 * i + 32 + lane] = oEB;
        st[128 * i + 64 + lane] = oDA;
        st[128 * i + 96 + lane] = oDB;
    }

    // One bulk store per warp: 8 KB contiguous (output rows 2m0 .. 2m0+7).
    asm volatile("fence.proxy.async.shared::cta;" ::: "memory");
    __syncwarp();
    if (lane == 0) {
        void* gdst = (void*)(o + (size_t)(2 * m0) * W_OUT);
        asm volatile("cp.async.bulk.global.shared::cta.bulk_group [%0], [%1], 8192;"
                     :: "l"(gdst), "r"(smem_u32(st)) : "memory");
        asm volatile("cp.async.bulk.commit_group;" ::: "memory");
        asm volatile("cp.async.bulk.wait_group 0;" ::: "memory");
    }
    __syncwarp();
}

extern "C" void kernel_launch(void* const* d_in, const int* in_sizes, int n_in,
                              void* d_out, int out_size) {
    const float* x = (const float*)d_in[0];
    float* out = (float*)d_out;

    dim3 block(32, WARPS, 1);                   // 128 threads
    dim3 grid(1, H_IN / (WARPS * ROWS), BC);    // (1, 8, 1024)
    upfir_up2_kernel<<<grid, block>>>(x, out);
}